// round 1
// baseline (speedup 1.0000x reference)
#include <cuda_runtime.h>
#include <math.h>

#define M_PTS 2048
#define N_VOX 65536
#define TPB   128

// Per-point precomputed data: (qq, -2qx, -2qy, -2qz) with q = pred / RES
__device__ float4 g_pts[M_PTS];
// Accumulators: [0]=pred_sum, [1]=sum((free+occ)*obp), [2]=sum(mask*obp), [3]=mask_sum
__device__ double g_acc[4];

__global__ void setup_kernel(const float* __restrict__ quat,
                             const float* __restrict__ tran,
                             const float* __restrict__ model,
                             const float* __restrict__ view) {
    __shared__ float Ms[16];
    if (threadIdx.x == 0) {
        // quaternion matrix (fp64 for the tiny part; downstream compute fp32)
        double q[4]; double s = 0.0;
        for (int i = 0; i < 4; i++) { q[i] = (double)quat[i]; s += q[i] * q[i]; }
        double f = sqrt(2.0 / s);
        for (int i = 0; i < 4; i++) q[i] *= f;
        double Q[4][4];
        for (int i = 0; i < 4; i++)
            for (int j = 0; j < 4; j++) Q[i][j] = q[i] * q[j];
        double E[4][4] = {
            {1.0 - Q[2][2] - Q[3][3], Q[1][2] - Q[3][0],       Q[1][3] + Q[2][0],       (double)tran[0]},
            {Q[1][2] + Q[3][0],       1.0 - Q[1][1] - Q[3][3], Q[2][3] - Q[1][0],       (double)tran[1]},
            {Q[1][3] - Q[2][0],       Q[2][3] + Q[1][0],       1.0 - Q[1][1] - Q[2][2], (double)tran[2]},
            {0.0, 0.0, 0.0, 1.0}};
        // invert view (4x4 Gauss-Jordan, partial pivot, fp64)
        double A[4][8];
        for (int i = 0; i < 4; i++) {
            for (int j = 0; j < 4; j++) {
                A[i][j]     = (double)view[i * 4 + j];
                A[i][j + 4] = (i == j) ? 1.0 : 0.0;
            }
        }
        for (int col = 0; col < 4; col++) {
            int piv = col; double best = fabs(A[col][col]);
            for (int r = col + 1; r < 4; r++)
                if (fabs(A[r][col]) > best) { best = fabs(A[r][col]); piv = r; }
            if (piv != col)
                for (int j = 0; j < 8; j++) { double t = A[col][j]; A[col][j] = A[piv][j]; A[piv][j] = t; }
            double d = 1.0 / A[col][col];
            for (int j = 0; j < 8; j++) A[col][j] *= d;
            for (int r = 0; r < 4; r++) {
                if (r == col) continue;
                double m = A[r][col];
                for (int j = 0; j < 8; j++) A[r][j] -= m * A[col][j];
            }
        }
        // W = inv(view) @ E
        for (int i = 0; i < 4; i++)
            for (int j = 0; j < 4; j++) {
                double acc = 0.0;
                for (int k = 0; k < 4; k++) acc += A[i][k + 4] * E[k][j];
                Ms[i * 4 + j] = (float)acc;
            }
        g_acc[0] = 0.0; g_acc[1] = 0.0; g_acc[2] = 0.0; g_acc[3] = 0.0;
    }
    __syncthreads();
    for (int i = threadIdx.x; i < M_PTS; i += blockDim.x) {
        float mx = model[3 * i + 0], my = model[3 * i + 1], mz = model[3 * i + 2];
        float hx = Ms[0]  * mx + Ms[1]  * my + Ms[2]  * mz + Ms[3];
        float hy = Ms[4]  * mx + Ms[5]  * my + Ms[6]  * mz + Ms[7];
        float hz = Ms[8]  * mx + Ms[9]  * my + Ms[10] * mz + Ms[11];
        float hw = Ms[12] * mx + Ms[13] * my + Ms[14] * mz + Ms[15];
        float px = hx / hw, py = hy / hw, pz = hz / hw;
        // q = pred / RES, RES = 0.5
        float qx = px * 2.0f, qy = py * 2.0f, qz = pz * 2.0f;
        float qq = qx * qx + qy * qy + qz * qz;
        g_pts[i] = make_float4(qq, -2.0f * qx, -2.0f * qy, -2.0f * qz);
    }
}

__global__ __launch_bounds__(TPB) void dist_kernel(
    const float* __restrict__ centers, const float* __restrict__ freev,
    const float* __restrict__ occo,    const float* __restrict__ masks) {
    __shared__ float4 sp[M_PTS];
    __shared__ float  red[4][TPB / 32];
    for (int i = threadIdx.x; i < M_PTS; i += TPB) sp[i] = g_pts[i];
    __syncthreads();

    const int v0 = blockIdx.x * (TPB * 2) + threadIdx.x;
    const int v1 = v0 + TPB;

    // u = center / RES = center * 2
    float ux0 = centers[3 * v0 + 0] * 2.0f;
    float uy0 = centers[3 * v0 + 1] * 2.0f;
    float uz0 = centers[3 * v0 + 2] * 2.0f;
    float ux1 = centers[3 * v1 + 0] * 2.0f;
    float uy1 = centers[3 * v1 + 1] * 2.0f;
    float uz1 = centers[3 * v1 + 2] * 2.0f;

    float m0 = 3.4e38f, m1 = 3.4e38f;
#pragma unroll 8
    for (int i = 0; i < M_PTS; i++) {
        float4 p = sp[i];
        float w0 = fmaf(ux0, p.y, p.x);
        w0 = fmaf(uy0, p.z, w0);
        w0 = fmaf(uz0, p.w, w0);
        float w1 = fmaf(ux1, p.y, p.x);
        w1 = fmaf(uy1, p.z, w1);
        w1 = fmaf(uz1, p.w, w1);
        m0 = fminf(m0, w0);
        m1 = fminf(m1, w1);
    }

    float uu0 = ux0 * ux0 + uy0 * uy0 + uz0 * uz0;
    float uu1 = ux1 * ux1 + uy1 * uy1 + uz1 * uz1;
    float d0 = sqrtf(fmaxf(uu0 + m0, 0.0f)); d0 = fminf(d0, 0.25f);
    float d1 = sqrtf(fmaxf(uu1 + m1, 0.0f)); d1 = fminf(d1, 0.25f);
    // obp = max(1 - dmin/(RES/2), 0) = max(1 - 4*dmin, 0)
    float o0 = fmaxf(1.0f - 4.0f * d0, 0.0f);
    float o1 = fmaxf(1.0f - 4.0f * d1, 0.0f);

    float msk0 = masks[v0], msk1 = masks[v1];
    float ps = o0 + o1;
    float s1 = (freev[v0] + occo[v0]) * o0 + (freev[v1] + occo[v1]) * o1;
    float s2 = msk0 * o0 + msk1 * o1;
    float ms = msk0 + msk1;

    const unsigned full = 0xffffffffu;
#pragma unroll
    for (int off = 16; off > 0; off >>= 1) {
        ps += __shfl_down_sync(full, ps, off);
        s1 += __shfl_down_sync(full, s1, off);
        s2 += __shfl_down_sync(full, s2, off);
        ms += __shfl_down_sync(full, ms, off);
    }
    int lane = threadIdx.x & 31, w = threadIdx.x >> 5;
    if (lane == 0) { red[0][w] = ps; red[1][w] = s1; red[2][w] = s2; red[3][w] = ms; }
    __syncthreads();
    if (threadIdx.x == 0) {
        float tps = 0.f, ts1 = 0.f, ts2 = 0.f, tms = 0.f;
        for (int i = 0; i < TPB / 32; i++) {
            tps += red[0][i]; ts1 += red[1][i]; ts2 += red[2][i]; tms += red[3][i];
        }
        atomicAdd(&g_acc[0], (double)tps);
        atomicAdd(&g_acc[1], (double)ts1);
        atomicAdd(&g_acc[2], (double)ts2);
        atomicAdd(&g_acc[3], (double)tms);
    }
}

__global__ void final_kernel(float* __restrict__ out) {
    double ps = g_acc[0], s1 = g_acc[1], s2 = g_acc[2], ms = g_acc[3];
    double t1 = (ps > 0.0) ? s1 / ps : 0.0;
    double t2 = (ms > 0.0) ? s2 / ms : 0.0;
    out[0] = (float)(t1 - t2);
}

extern "C" void kernel_launch(void* const* d_in, const int* in_sizes, int n_in,
                              void* d_out, int out_size) {
    const float* quat    = (const float*)d_in[0];
    const float* tran    = (const float*)d_in[1];
    const float* model   = (const float*)d_in[2];
    const float* view    = (const float*)d_in[3];
    const float* centers = (const float*)d_in[4];
    const float* freev   = (const float*)d_in[5];
    const float* occo    = (const float*)d_in[6];
    const float* masks   = (const float*)d_in[7];
    (void)in_sizes; (void)n_in; (void)out_size;

    setup_kernel<<<1, 256>>>(quat, tran, model, view);
    dist_kernel<<<N_VOX / (TPB * 2), TPB>>>(centers, freev, occo, masks);
    final_kernel<<<1, 1>>>((float*)d_out);
}

// round 4
// speedup vs baseline: 1.5919x; 1.5919x over previous
#include <cuda_runtime.h>
#include <math.h>

#define M_PTS 2048
#define N_VOX 65536
#define TPB   128
#define GRID  (N_VOX / (TPB * 2))   // 256 blocks, 2 voxels/thread

// Per-block partial sums: {pred_sum, sum((free+occ)*obp), sum(mask*obp), mask_sum}
__device__ float4 g_part[GRID];

// ---------- f32x2 helpers (sm_100+ packed fp32) ----------
__device__ __forceinline__ unsigned long long pack2f(float a, float b) {
    unsigned long long r;
    asm("mov.b64 %0, {%1, %2};" : "=l"(r) : "f"(a), "f"(b));
    return r;
}
__device__ __forceinline__ unsigned long long fma2(unsigned long long a,
                                                   unsigned long long b,
                                                   unsigned long long c) {
    unsigned long long d;
    asm("fma.rn.f32x2 %0, %1, %2, %3;" : "=l"(d) : "l"(a), "l"(b), "l"(c));
    return d;
}
__device__ __forceinline__ void unpack2f(unsigned long long v, float& x, float& y) {
    asm("mov.b64 {%0, %1}, %2;" : "=f"(x), "=f"(y) : "l"(v));
}
__device__ __forceinline__ void lds2u64(unsigned addr, unsigned long long& a,
                                        unsigned long long& b) {
    asm volatile("ld.shared.v2.u64 {%0, %1}, [%2];" : "=l"(a), "=l"(b) : "r"(addr));
}

__global__ __launch_bounds__(TPB) void fused_kernel(
    const float* __restrict__ quat,    const float* __restrict__ tran,
    const float* __restrict__ model,   const float* __restrict__ view,
    const float* __restrict__ centers, const float* __restrict__ freev,
    const float* __restrict__ occo,    const float* __restrict__ masks) {
    // Packed point tables: sA[j] = {mxA, mxB, myA, myB}, sB[j] = {mzA, mzB, ppA, ppB}
    // for points A=2j, B=2j+1, with m* = -2*q*, pp = |q|^2, q = pred/RES.
    __shared__ float4 sA[M_PTS / 2];
    __shared__ float4 sB[M_PTS / 2];
    __shared__ float  Ms[16];
    __shared__ float  red[4][TPB / 32];

    const int t = threadIdx.x;
    const int v0 = blockIdx.x * (TPB * 2) + t;
    const int v1 = v0 + TPB;

    // Issue voxel-side global loads early (independent of the matrix).
    float ux0 = centers[3 * v0 + 0] * 2.0f;
    float uy0 = centers[3 * v0 + 1] * 2.0f;
    float uz0 = centers[3 * v0 + 2] * 2.0f;
    float ux1 = centers[3 * v1 + 0] * 2.0f;
    float uy1 = centers[3 * v1 + 1] * 2.0f;
    float uz1 = centers[3 * v1 + 2] * 2.0f;
    float fo0 = freev[v0] + occo[v0];
    float fo1 = freev[v1] + occo[v1];
    float mk0 = masks[v0], mk1 = masks[v1];

    // One thread builds mat_world = inv(view) @ quat_matrix in fp32.
    if (t == 0) {
        float q[4]; float s = 0.0f;
#pragma unroll
        for (int i = 0; i < 4; i++) { q[i] = quat[i]; s += q[i] * q[i]; }
        float f = sqrtf(2.0f / s);
#pragma unroll
        for (int i = 0; i < 4; i++) q[i] *= f;
        float Q[4][4];
#pragma unroll
        for (int i = 0; i < 4; i++)
#pragma unroll
            for (int j = 0; j < 4; j++) Q[i][j] = q[i] * q[j];
        float E[4][4] = {
            {1.0f - Q[2][2] - Q[3][3], Q[1][2] - Q[3][0],        Q[1][3] + Q[2][0],        tran[0]},
            {Q[1][2] + Q[3][0],        1.0f - Q[1][1] - Q[3][3], Q[2][3] - Q[1][0],        tran[1]},
            {Q[1][3] - Q[2][0],        Q[2][3] + Q[1][0],        1.0f - Q[1][1] - Q[2][2], tran[2]},
            {0.0f, 0.0f, 0.0f, 1.0f}};
        // Gauss-Jordan inverse of view (4x4, partial pivot, fp32)
        float A[4][8];
        for (int i = 0; i < 4; i++)
            for (int j = 0; j < 4; j++) {
                A[i][j]     = view[i * 4 + j];
                A[i][j + 4] = (i == j) ? 1.0f : 0.0f;
            }
        for (int col = 0; col < 4; col++) {
            int piv = col; float best = fabsf(A[col][col]);
            for (int r = col + 1; r < 4; r++)
                if (fabsf(A[r][col]) > best) { best = fabsf(A[r][col]); piv = r; }
            if (piv != col)
                for (int j = 0; j < 8; j++) { float tmp = A[col][j]; A[col][j] = A[piv][j]; A[piv][j] = tmp; }
            float d = 1.0f / A[col][col];
            for (int j = 0; j < 8; j++) A[col][j] *= d;
            for (int r = 0; r < 4; r++) {
                if (r == col) continue;
                float m = A[r][col];
                for (int j = 0; j < 8; j++) A[r][j] -= m * A[col][j];
            }
        }
        for (int i = 0; i < 4; i++)
            for (int j = 0; j < 4; j++) {
                float acc = 0.0f;
                for (int k = 0; k < 4; k++) acc += A[i][k + 4] * E[k][j];
                Ms[i * 4 + j] = acc;
            }
    }
    __syncthreads();

    // Transform all model points; write packed pair tables.
    for (int i = t; i < M_PTS; i += TPB) {
        float mx = model[3 * i + 0], my = model[3 * i + 1], mz = model[3 * i + 2];
        float hx = Ms[0]  * mx + Ms[1]  * my + Ms[2]  * mz + Ms[3];
        float hy = Ms[4]  * mx + Ms[5]  * my + Ms[6]  * mz + Ms[7];
        float hz = Ms[8]  * mx + Ms[9]  * my + Ms[10] * mz + Ms[11];
        float hw = Ms[12] * mx + Ms[13] * my + Ms[14] * mz + Ms[15];
        float inv = 1.0f / hw;
        float qx = hx * inv * 2.0f;   // pred / RES
        float qy = hy * inv * 2.0f;
        float qz = hz * inv * 2.0f;
        float pp = qx * qx + qy * qy + qz * qz;
        int j = i >> 1, h = i & 1;
        if (h == 0) {
            sA[j].x = -2.0f * qx; sA[j].z = -2.0f * qy;
            sB[j].x = -2.0f * qz; sB[j].z = pp;
        } else {
            sA[j].y = -2.0f * qx; sA[j].w = -2.0f * qy;
            sB[j].y = -2.0f * qz; sB[j].w = pp;
        }
    }
    __syncthreads();

    // Loop-invariant packed voxel coords (broadcast into both lanes).
    const unsigned long long cxx0 = pack2f(ux0, ux0), cyy0 = pack2f(uy0, uy0), czz0 = pack2f(uz0, uz0);
    const unsigned long long cxx1 = pack2f(ux1, ux1), cyy1 = pack2f(uy1, uy1), czz1 = pack2f(uz1, uz1);

    unsigned aA = (unsigned)__cvta_generic_to_shared(sA);
    unsigned aB = (unsigned)__cvta_generic_to_shared(sB);

    float m00 = 3.4e38f, m01 = 3.4e38f, m10 = 3.4e38f, m11 = 3.4e38f;
#pragma unroll 8
    for (int j = 0; j < M_PTS / 2; j++) {
        unsigned long long pa0, pa1, pb0, pb1;
        lds2u64(aA + j * 16, pa0, pa1);   // {mxA,mxB}, {myA,myB}
        lds2u64(aB + j * 16, pb0, pb1);   // {mzA,mzB}, {ppA,ppB}
        unsigned long long w0 = fma2(czz0, pb0, pb1);
        unsigned long long w1 = fma2(czz1, pb0, pb1);
        w0 = fma2(cyy0, pa1, w0);
        w1 = fma2(cyy1, pa1, w1);
        w0 = fma2(cxx0, pa0, w0);
        w1 = fma2(cxx1, pa0, w1);
        float a, b;
        unpack2f(w0, a, b);
        m00 = fminf(m00, a); m01 = fminf(m01, b);
        unpack2f(w1, a, b);
        m10 = fminf(m10, a); m11 = fminf(m11, b);
    }
    float m0 = fminf(m00, m01);
    float m1 = fminf(m10, m11);

    float uu0 = ux0 * ux0 + uy0 * uy0 + uz0 * uz0;
    float uu1 = ux1 * ux1 + uy1 * uy1 + uz1 * uz1;
    float d0 = sqrtf(fmaxf(uu0 + m0, 0.0f)); d0 = fminf(d0, 0.25f);
    float d1 = sqrtf(fmaxf(uu1 + m1, 0.0f)); d1 = fminf(d1, 0.25f);
    float o0 = fmaxf(1.0f - 4.0f * d0, 0.0f);
    float o1 = fmaxf(1.0f - 4.0f * d1, 0.0f);

    float ps = o0 + o1;
    float s1 = fo0 * o0 + fo1 * o1;
    float s2 = mk0 * o0 + mk1 * o1;
    float msum = mk0 + mk1;

    const unsigned full = 0xffffffffu;
#pragma unroll
    for (int off = 16; off > 0; off >>= 1) {
        ps   += __shfl_down_sync(full, ps, off);
        s1   += __shfl_down_sync(full, s1, off);
        s2   += __shfl_down_sync(full, s2, off);
        msum += __shfl_down_sync(full, msum, off);
    }
    int lane = t & 31, w = t >> 5;
    if (lane == 0) { red[0][w] = ps; red[1][w] = s1; red[2][w] = s2; red[3][w] = msum; }
    __syncthreads();
    if (t == 0) {
        float tps = 0.f, ts1 = 0.f, ts2 = 0.f, tms = 0.f;
#pragma unroll
        for (int i = 0; i < TPB / 32; i++) {
            tps += red[0][i]; ts1 += red[1][i]; ts2 += red[2][i]; tms += red[3][i];
        }
        g_part[blockIdx.x] = make_float4(tps, ts1, ts2, tms);
    }
}

__global__ __launch_bounds__(GRID) void final_kernel(float* __restrict__ out) {
    __shared__ float4 red[GRID / 32];
    int t = threadIdx.x;
    float4 p = g_part[t];
    const unsigned full = 0xffffffffu;
#pragma unroll
    for (int off = 16; off > 0; off >>= 1) {
        p.x += __shfl_down_sync(full, p.x, off);
        p.y += __shfl_down_sync(full, p.y, off);
        p.z += __shfl_down_sync(full, p.z, off);
        p.w += __shfl_down_sync(full, p.w, off);
    }
    int lane = t & 31, w = t >> 5;
    if (lane == 0) red[w] = p;
    __syncthreads();
    if (t == 0) {
        double ps = 0.0, s1 = 0.0, s2 = 0.0, ms = 0.0;
#pragma unroll
        for (int i = 0; i < GRID / 32; i++) {
            ps += (double)red[i].x; s1 += (double)red[i].y;
            s2 += (double)red[i].z; ms += (double)red[i].w;
        }
        double t1 = (ps > 0.0) ? s1 / ps : 0.0;
        double t2 = (ms > 0.0) ? s2 / ms : 0.0;
        out[0] = (float)(t1 - t2);
    }
}

extern "C" void kernel_launch(void* const* d_in, const int* in_sizes, int n_in,
                              void* d_out, int out_size) {
    const float* quat    = (const float*)d_in[0];
    const float* tran    = (const float*)d_in[1];
    const float* model   = (const float*)d_in[2];
    const float* view    = (const float*)d_in[3];
    const float* centers = (const float*)d_in[4];
    const float* freev   = (const float*)d_in[5];
    const float* occo    = (const float*)d_in[6];
    const float* masks   = (const float*)d_in[7];
    (void)in_sizes; (void)n_in; (void)out_size;

    fused_kernel<<<GRID, TPB>>>(quat, tran, model, view, centers, freev, occo, masks);
    final_kernel<<<1, GRID>>>((float*)d_out);
}